// round 12
// baseline (speedup 1.0000x reference)
#include <cuda_runtime.h>
#include <stdint.h>

#define VOCAB 512
#define WCHARS 24
#define WPB 8          // warps per block

// Two-node graph:
//   node 1: cudaMemsetAsync zero-fills the output via the dense-fill engine
//           (~10 TB/s, beats any SM-issued store path at ~5.4 TB/s).
//   node 2: this kernel writes <=24 PLAIN STG.32 per row (no atomics -> no
//           read-for-ownership -> no DRAM refetch). Duplicate chars within a
//           row are pre-summed in-warp via __match_any_sync + shfl so each
//           bin gets exactly one store. Tail (lengths) fused here.
// int64 inputs arrive as int32 (jax x64 disabled).
__global__ void __launch_bounds__(WPB * 32)
fofe_scatter_kernel(const int* __restrict__ sents,
                    const int* __restrict__ lengths,
                    const float* __restrict__ alpha_p,
                    float* __restrict__ out,
                    int nrows,
                    long long main_elems,
                    int extra,
                    int nlen)
{
    const int warp = threadIdx.x >> 5;
    const int lane = threadIdx.x & 31;
    const int row  = blockIdx.x * WPB + warp;

    // tail: (out, lengths) second output appended to d_out (overwrites zeros)
    if (blockIdx.x == 0 && (int)threadIdx.x < extra) {
        int i = threadIdx.x;
        out[main_elems + i] = (i < nlen) ? (float)lengths[i] : 0.0f;
    }
    if (row >= nrows) return;

    int c = 0;
    if (lane < WCHARS)
        c = sents[(long long)row * WCHARS + lane];
    const float a = __ldg(alpha_p);

    const bool valid = (lane < WCHARS) && (c > 0) && (c < VOCAB);
    const unsigned nz = __ballot_sync(0xffffffffu, valid);

    if (valid) {
        // weight for this char: alpha^(# nonzero chars strictly after it)
        const int suffix = __popc(nz & (0xfffffffeu << lane));
        const float w = (suffix == 0) ? 1.0f
                                      : exp2f(log2f(a) * (float)suffix);

        // group lanes holding the same char; elect lowest lane as leader
        const unsigned grp    = __match_any_sync(nz, c);
        const int      leader = __ffs(grp) - 1;

        // sum weights of my group. All valid lanes iterate the SAME set (nz),
        // so the shfl participation is uniform; each lane filters by char.
        float wsum = 0.0f;
        unsigned m = nz;
        while (m) {
            const int j = __ffs(m) - 1;
            m &= m - 1;
            const int   cj = __shfl_sync(nz, c, j);
            const float wj = __shfl_sync(nz, w, j);
            if (cj == c) wsum += wj;
        }

        if (lane == leader)
            out[(long long)row * VOCAB + c] = wsum;   // plain store, no RMW
    }
}

extern "C" void kernel_launch(void* const* d_in, const int* in_sizes, int n_in,
                              void* d_out, int out_size)
{
    const int*   sents   = (const int*)d_in[0];
    const int*   lengths = (const int*)d_in[1];
    const float* alpha   = (const float*)d_in[2];
    float*       out     = (float*)d_out;

    const int nrows = in_sizes[0] / WCHARS;             // B*S = 32768
    const long long main_elems = (long long)nrows * VOCAB;
    const int nlen = in_sizes[1];

    long long extra_ll = (long long)out_size - main_elems;
    if (extra_ll < 0) extra_ll = 0;
    if (extra_ll > WPB * 32) extra_ll = WPB * 32;

    // node 1: dense zero-fill via the copy/fill engine path
    cudaMemsetAsync(d_out, 0, (size_t)out_size * sizeof(float), 0);

    // node 2: sparse exact-value scatter + tail
    const int blocks = (nrows + WPB - 1) / WPB;
    fofe_scatter_kernel<<<blocks, WPB * 32>>>(sents, lengths, alpha, out,
                                              nrows, main_elems,
                                              (int)extra_ll, nlen);
}

// round 13
// speedup vs baseline: 1.8153x; 1.8153x over previous
#include <cuda_runtime.h>
#include <stdint.h>

#define VOCAB 512
#define WCHARS 24
#define WPB 8          // warps per block

// One warp per (b,s) row: 512-bin smem histogram, then coalesced STG.128
// drain using WRITE-THROUGH stores (st.global.wt). Rationale: timed graph
// replays run back-to-back, so normal/streaming stores must evict the
// previous replay's dirty L2 lines mid-kernel (the ~14.7us plateau). WT
// leaves no dirty lines: each replay writes straight toward DRAM
// (write-combined full sectors), next replay's stores see a clean L2.
// Tail output (lengths) fused into block 0. int64 inputs arrive as int32
// (jax x64 disabled).
__global__ void __launch_bounds__(WPB * 32)
fofe_kernel(const int* __restrict__ sents,
            const int* __restrict__ lengths,
            const float* __restrict__ alpha_p,
            float* __restrict__ out,
            int nrows,
            long long main_elems,
            int extra,
            int nlen)
{
    __shared__ __align__(128) float hist[WPB][VOCAB];   // 16 KB

    const int warp = threadIdx.x >> 5;
    const int lane = threadIdx.x & 31;
    const int row  = blockIdx.x * WPB + warp;

    // fused tail: (out, lengths) second output appended to d_out
    if (blockIdx.x == 0 && (int)threadIdx.x < extra) {
        int i = threadIdx.x;
        out[main_elems + i] = (i < nlen) ? (float)lengths[i] : 0.0f;
    }
    if (row >= nrows) return;

    float* h = hist[warp];

    // input load first; zero-fill overlaps its latency
    int c = 0;
    if (lane < WCHARS)
        c = sents[(long long)row * WCHARS + lane];
    const float a = __ldg(alpha_p);

    // zero the 2KB row histogram: 4 x STS.128 per lane
    float4* h4 = reinterpret_cast<float4*>(h);
    const float4 z = make_float4(0.f, 0.f, 0.f, 0.f);
    #pragma unroll
    for (int j = 0; j < 4; ++j)
        h4[j * 32 + lane] = z;

    const bool valid = (lane < WCHARS) && (c > 0) && (c < VOCAB);
    const unsigned nz = __ballot_sync(0xffffffffu, valid);
    __syncwarp();                       // zeros visible before atomics

    if (valid) {
        const int suffix = __popc(nz & (0xfffffffeu << lane));
        const float w = (suffix == 0) ? 1.0f
                                      : exp2f(log2f(a) * (float)suffix);
        atomicAdd(&h[c], w);            // shared atomic, <=24 per row
    }
    __syncwarp();

    // drain: 4 x LDS.128 -> st.global.wt.v4 per lane, coalesced 128B segments
    float* orow = out + (long long)row * VOCAB;
    #pragma unroll
    for (int i = 0; i < 4; ++i) {
        const float4 v = h4[i * 32 + lane];
        float* dst = orow + (i * 32 + lane) * 4;
        asm volatile(
            "st.global.wt.v4.f32 [%0], {%1, %2, %3, %4};"
            :: "l"(dst), "f"(v.x), "f"(v.y), "f"(v.z), "f"(v.w)
            : "memory");
    }
}

extern "C" void kernel_launch(void* const* d_in, const int* in_sizes, int n_in,
                              void* d_out, int out_size)
{
    const int*   sents   = (const int*)d_in[0];
    const int*   lengths = (const int*)d_in[1];
    const float* alpha   = (const float*)d_in[2];
    float*       out     = (float*)d_out;

    const int nrows = in_sizes[0] / WCHARS;             // B*S = 32768
    const long long main_elems = (long long)nrows * VOCAB;
    const int nlen = in_sizes[1];

    long long extra_ll = (long long)out_size - main_elems;
    if (extra_ll < 0) extra_ll = 0;
    if (extra_ll > WPB * 32) extra_ll = WPB * 32;

    const int blocks = (nrows + WPB - 1) / WPB;
    fofe_kernel<<<blocks, WPB * 32>>>(sents, lengths, alpha, out,
                                      nrows, main_elems, (int)extra_ll, nlen);
}